// round 6
// baseline (speedup 1.0000x reference)
#include <cuda_runtime.h>
#include <cstdint>
#include <cstddef>

// Problem constants
constexpr int B_ = 64;
constexpr int L_ = 512;
constexpr int E_ = 512;
constexpr int H_ = 512;
constexpr int G_ = 1536;          // 3*H
constexpr int M_ = B_ * L_;       // 32768 rows per direction
constexpr float LN_EPS = 1e-5f;

// Scratch (device globals: allocation-free)
__device__ float g_px[2ull * 32768ull * 1536ull];   // LN3(x @ Wx) per dir, [dir][b*L+s][1536]
__device__ float g_ph[2 * 64 * 1536];               // per-step h @ Wh, [dir][b][1536]
__device__ float g_hT[2 * 512 * 64];                // hidden state transposed [dir][k][b]
__device__ unsigned g_cnt;                          // grid barrier (zero-init)
__device__ unsigned g_gen;

// ---------------------------------------------------------------------------
// Kernel 1: px[dir][m][n] = sum_e xs[b][torig][e] * Wx_dir[e][n]
// BM=128, BN=64, BK=16, 256 threads, 8x4 per-thread tile.
// ---------------------------------------------------------------------------
__global__ __launch_bounds__(256) void gemm_px_kernel(
    const float* __restrict__ xs,
    const float* __restrict__ Wxf,
    const float* __restrict__ Wxb)
{
    constexpr int BM = 128, BN = 64, BK = 16, LDA = BM + 4;
    __shared__ float As[BK * LDA];
    __shared__ float Bs[BK * BN];

    const int dir = blockIdx.z;
    const float* W = dir ? Wxb : Wxf;
    const int m0 = blockIdx.y * BM;
    const int n0 = blockIdx.x * BN;
    const int t  = threadIdx.x;
    const int tx = t & 15;     // 16 col groups (4 cols each)
    const int ty = t >> 4;     // 16 row groups (8 rows each)

    float acc[8][4];
#pragma unroll
    for (int r = 0; r < 8; r++)
#pragma unroll
        for (int c = 0; c < 4; c++) acc[r][c] = 0.f;

    for (int kt = 0; kt < E_; kt += BK) {
        // Load A tile (gathered rows, reversed in t for dir=1)
#pragma unroll
        for (int i = 0; i < 2; i++) {
            int idx = t + 256 * i;        // 0..511 -> 128 rows x 4 float4
            int row = idx >> 2;
            int c4  = idx & 3;
            int m   = m0 + row;
            int b   = m >> 9;
            int s   = m & 511;
            int torig = dir ? (511 - s) : s;
            const float4 va = *reinterpret_cast<const float4*>(
                xs + ((size_t)(b * 512 + torig)) * 512 + kt + c4 * 4);
            As[(c4 * 4 + 0) * LDA + row] = va.x;
            As[(c4 * 4 + 1) * LDA + row] = va.y;
            As[(c4 * 4 + 2) * LDA + row] = va.z;
            As[(c4 * 4 + 3) * LDA + row] = va.w;
        }
        // Load B tile
        {
            int row = t >> 4;   // 0..15 (k)
            int c4  = t & 15;   // 16 float4 per row
            const float4 vb = *reinterpret_cast<const float4*>(
                W + (size_t)(kt + row) * G_ + n0 + c4 * 4);
            *reinterpret_cast<float4*>(Bs + row * BN + c4 * 4) = vb;
        }
        __syncthreads();

#pragma unroll
        for (int k = 0; k < BK; k++) {
            float4 a0 = *reinterpret_cast<const float4*>(As + k * LDA + ty * 8);
            float4 a1 = *reinterpret_cast<const float4*>(As + k * LDA + ty * 8 + 4);
            float4 bv = *reinterpret_cast<const float4*>(Bs + k * BN + tx * 4);
            float a[8] = {a0.x, a0.y, a0.z, a0.w, a1.x, a1.y, a1.z, a1.w};
            float bq[4] = {bv.x, bv.y, bv.z, bv.w};
#pragma unroll
            for (int r = 0; r < 8; r++)
#pragma unroll
                for (int c = 0; c < 4; c++) acc[r][c] += a[r] * bq[c];
        }
        __syncthreads();
    }

    float* C = g_px + (size_t)dir * M_ * G_;
#pragma unroll
    for (int r = 0; r < 8; r++) {
        float4 o;
        o.x = acc[r][0]; o.y = acc[r][1]; o.z = acc[r][2]; o.w = acc[r][3];
        *reinterpret_cast<float4*>(C + (size_t)(m0 + ty * 8 + r) * G_ + n0 + tx * 4) = o;
    }
}

// ---------------------------------------------------------------------------
// Kernel 2: in-place LN3 over g_px. One block per (row, chunk). 128 threads.
// ---------------------------------------------------------------------------
__global__ __launch_bounds__(128) void ln3_kernel(
    const float* __restrict__ gf, const float* __restrict__ bf,
    const float* __restrict__ gb, const float* __restrict__ bb)
{
    const int blk   = blockIdx.x;
    const int chunk = blk % 3;
    const int row   = blk / 3;          // 0..65535 (dir*32768 + m)
    const int dir   = row >> 15;
    const float* g  = (dir ? gb : gf) + chunk * 512;
    const float* be = (dir ? bb : bf) + chunk * 512;
    float* p = g_px + (size_t)row * G_ + chunk * 512;

    const int t = threadIdx.x;
    float4 v = reinterpret_cast<float4*>(p)[t];
    float s = v.x + v.y + v.z + v.w;
    float q = v.x * v.x + v.y * v.y + v.z * v.z + v.w * v.w;
#pragma unroll
    for (int o = 16; o > 0; o >>= 1) {
        s += __shfl_down_sync(0xffffffffu, s, o);
        q += __shfl_down_sync(0xffffffffu, q, o);
    }
    __shared__ float ss[4], sq[4];
    __shared__ float st[2];
    const int w = t >> 5, lane = t & 31;
    if (lane == 0) { ss[w] = s; sq[w] = q; }
    __syncthreads();
    if (t == 0) {
        float S = ss[0] + ss[1] + ss[2] + ss[3];
        float Q = sq[0] + sq[1] + sq[2] + sq[3];
        float mu = S * (1.f / 512.f);
        float var = Q * (1.f / 512.f) - mu * mu;
        st[0] = mu;
        st[1] = rsqrtf(var + LN_EPS);
    }
    __syncthreads();
    const float mu = st[0], rs = st[1];
    float4 gv = reinterpret_cast<const float4*>(g)[t];
    float4 bv = reinterpret_cast<const float4*>(be)[t];
    v.x = (v.x - mu) * rs * gv.x + bv.x;
    v.y = (v.y - mu) * rs * gv.y + bv.y;
    v.z = (v.z - mu) * rs * gv.z + bv.z;
    v.w = (v.w - mu) * rs * gv.w + bv.w;
    reinterpret_cast<float4*>(p)[t] = v;
}

// ---------------------------------------------------------------------------
// Kernel 3: persistent recurrence. Grid = 128 blocks (<= SM count -> all
// co-resident), 256 threads. Software grid barrier via global atomics.
//
// Per step:
//   Phase G: block (dir, slice) computes ph[dir][b][j0..j0+23] for all b,
//            with its Wh slice permanently in SMEM and hT staged via SMEM.
//   barrier
//   Phase U: block (dir, b) reads ph row, does LN3 stats + GRU gates,
//            keeps h in registers, writes hT (transposed) + output.
//   barrier
// ---------------------------------------------------------------------------
constexpr int NBLK  = 128;
constexpr int SLICE = 24;   // 64 slices * 24 = 1536

__device__ __forceinline__ void gridbar()
{
    __syncthreads();
    if (threadIdx.x == 0) {
        unsigned gen = *(volatile unsigned*)&g_gen;
        __threadfence();
        if (atomicAdd(&g_cnt, 1u) == NBLK - 1) {
            g_cnt = 0u;
            __threadfence();
            *(volatile unsigned*)&g_gen = gen + 1u;
        } else {
            while (*(volatile unsigned*)&g_gen == gen) { __nanosleep(64); }
            __threadfence();
        }
    }
    __syncthreads();
}

__global__ __launch_bounds__(256) void rnn_kernel(
    const float* __restrict__ Whf, const float* __restrict__ Whb,
    const float* __restrict__ ghf, const float* __restrict__ bhf,
    const float* __restrict__ ghb, const float* __restrict__ bhb,
    const float* __restrict__ mask, float* __restrict__ out)
{
    extern __shared__ float smem[];
    float* sWh = smem;                  // 512 * 24
    float* sh  = smem + 512 * SLICE;    // 64 * 64 staged hT chunk
    __shared__ float sred[48];
    __shared__ float sstat[6];

    const int t   = threadIdx.x;
    const int blk = blockIdx.x;
    const int dir = blk >> 6;
    const int sub = blk & 63;           // GEMM: slice id. Update: batch row.
    const float* Wh = dir ? Whb : Whf;
    const float* gh = dir ? ghb : ghf;
    const float* bh = dir ? bhb : bhf;
    const int j0 = sub * SLICE;

    // One-time: load persistent Wh slice into SMEM
    for (int i = t; i < 512 * SLICE; i += 256) {
        int k  = i / SLICE;
        int jj = i - k * SLICE;
        sWh[i] = Wh[(size_t)k * G_ + j0 + jj];
    }
    // One-time: zero hidden state (each block zeroes its 512-float slice)
    for (int i = t; i < 512; i += 256) g_hT[blk * 512 + i] = 0.f;

    // Update-phase constants (gains/biases for this thread's 6 columns)
    float gg6[6], bb6[6];
#pragma unroll
    for (int i = 0; i < 6; i++) {
        int j = (i >> 1) * 512 + (i & 1) * 256 + t;
        gg6[i] = gh[j];
        bb6[i] = bh[j];
    }
    const float* pxrow = g_px + ((size_t)(dir * 64 + sub)) * ((size_t)L_ * G_);
    const float* hTg = g_hT + dir * 512 * 64;
    float* phd = g_ph + dir * 64 * G_;
    const float* mrow = mask + sub * 512;

    float h0 = 0.f, h1 = 0.f;   // hidden state lives in registers (cols t, t+256)

    const int wj   = t >> 5;    // warp -> 3 consecutive j's
    const int lane = t & 31;    // lane -> 2 consecutive b's
    const float* wp = sWh + wj * 3;

    gridbar();   // hT zeros visible everywhere

    for (int s = 0; s < L_; s++) {
        // -------- Phase G: ph[b][j0+jloc] = sum_k hT[k][b] * Wh[k][j] --------
        float a00 = 0.f, a01 = 0.f, a10 = 0.f, a11 = 0.f, a20 = 0.f, a21 = 0.f;
        for (int k0 = 0; k0 < 512; k0 += 64) {
            const float4* src = reinterpret_cast<const float4*>(hTg + k0 * 64);
            float4* dst = reinterpret_cast<float4*>(sh);
#pragma unroll
            for (int i = 0; i < 4; i++) dst[t + 256 * i] = __ldcg(src + t + 256 * i);
            __syncthreads();
#pragma unroll 8
            for (int kk = 0; kk < 64; kk++) {
                const float* wr = wp + (k0 + kk) * SLICE;
                float w0 = wr[0], w1 = wr[1], w2 = wr[2];
                float2 hv = *reinterpret_cast<const float2*>(sh + kk * 64 + (lane << 1));
                a00 += w0 * hv.x; a01 += w0 * hv.y;
                a10 += w1 * hv.x; a11 += w1 * hv.y;
                a20 += w2 * hv.x; a21 += w2 * hv.y;
            }
            __syncthreads();
        }
        {
            int b0 = lane * 2;
            int jbase = j0 + wj * 3;
            float* pr0 = phd + (size_t)b0 * G_ + jbase;
            float* pr1 = pr0 + G_;
            pr0[0] = a00; pr0[1] = a10; pr0[2] = a20;
            pr1[0] = a01; pr1[1] = a11; pr1[2] = a21;
        }
        gridbar();

        // -------- Phase U: LN3(ph) + GRU gates for batch row `sub` --------
        const float* phr = phd + (size_t)sub * G_;
        float v0 = __ldcg(phr + t);
        float v1 = __ldcg(phr + 256 + t);
        float v2 = __ldcg(phr + 512 + t);
        float v3 = __ldcg(phr + 768 + t);
        float v4 = __ldcg(phr + 1024 + t);
        float v5 = __ldcg(phr + 1280 + t);

        float p0 = v0 + v1, p1 = v2 + v3, p2 = v4 + v5;
        float q0 = v0 * v0 + v1 * v1;
        float q1 = v2 * v2 + v3 * v3;
        float q2 = v4 * v4 + v5 * v5;
#pragma unroll
        for (int o = 16; o > 0; o >>= 1) {
            p0 += __shfl_down_sync(0xffffffffu, p0, o);
            p1 += __shfl_down_sync(0xffffffffu, p1, o);
            p2 += __shfl_down_sync(0xffffffffu, p2, o);
            q0 += __shfl_down_sync(0xffffffffu, q0, o);
            q1 += __shfl_down_sync(0xffffffffu, q1, o);
            q2 += __shfl_down_sync(0xffffffffu, q2, o);
        }
        if (lane == 0) {
            sred[wj * 6 + 0] = p0; sred[wj * 6 + 1] = p1; sred[wj * 6 + 2] = p2;
            sred[wj * 6 + 3] = q0; sred[wj * 6 + 4] = q1; sred[wj * 6 + 5] = q2;
        }
        __syncthreads();
        if (t < 6) {
            float tot = 0.f;
#pragma unroll
            for (int w = 0; w < 8; w++) tot += sred[w * 6 + t];
            sstat[t] = tot;
        }
        __syncthreads();
        const float mu0 = sstat[0] * (1.f / 512.f);
        const float mu1 = sstat[1] * (1.f / 512.f);
        const float mu2 = sstat[2] * (1.f / 512.f);
        const float rs0 = rsqrtf(sstat[3] * (1.f / 512.f) - mu0 * mu0 + LN_EPS);
        const float rs1 = rsqrtf(sstat[4] * (1.f / 512.f) - mu1 * mu1 + LN_EPS);
        const float rs2 = rsqrtf(sstat[5] * (1.f / 512.f) - mu2 * mu2 + LN_EPS);

        const int torig = dir ? (511 - s) : s;
        const float m = mrow[torig];
        const float* pxt = pxrow + (size_t)s * G_;
        float* outt = out + ((size_t)sub * 512 + torig) * 1024 + dir * 512;
        float* hwr = g_hT + dir * 512 * 64;

        // half 0: column c = t
        {
            float phz = (v0 - mu0) * rs0 * gg6[0] + bb6[0];
            float phrv = (v2 - mu1) * rs1 * gg6[2] + bb6[2];
            float phgv = (v4 - mu2) * rs2 * gg6[4] + bb6[4];
            float xz = pxt[t], xr = pxt[512 + t], xg = pxt[1024 + t];
            float z = 1.f / (1.f + __expf(-(xz + phz)));
            float r = 1.f / (1.f + __expf(-(xr + phrv)));
            float gv = tanhf(xg + r * phgv);
            h0 = h0 + m * z * (gv - h0);
            hwr[t * 64 + sub] = h0;
            outt[t] = h0 * m;
        }
        // half 1: column c = t + 256
        {
            int c = t + 256;
            float phz = (v1 - mu0) * rs0 * gg6[1] + bb6[1];
            float phrv = (v3 - mu1) * rs1 * gg6[3] + bb6[3];
            float phgv = (v5 - mu2) * rs2 * gg6[5] + bb6[5];
            float xz = pxt[c], xr = pxt[512 + c], xg = pxt[1024 + c];
            float z = 1.f / (1.f + __expf(-(xz + phz)));
            float r = 1.f / (1.f + __expf(-(xr + phrv)));
            float gv = tanhf(xg + r * phgv);
            h1 = h1 + m * z * (gv - h1);
            hwr[c * 64 + sub] = h1;
            outt[c] = h1 * m;
        }
        gridbar();
    }
}

// ---------------------------------------------------------------------------
extern "C" void kernel_launch(void* const* d_in, const int* in_sizes, int n_in,
                              void* d_out, int out_size)
{
    const float* xs    = (const float*)d_in[0];
    const float* xmask = (const float*)d_in[1];
    const float* fWx   = (const float*)d_in[2];
    const float* fWh   = (const float*)d_in[3];
    const float* fgx   = (const float*)d_in[4];
    const float* fbx   = (const float*)d_in[5];
    const float* fgh   = (const float*)d_in[6];
    const float* fbh   = (const float*)d_in[7];
    const float* bWx   = (const float*)d_in[8];
    const float* bWh   = (const float*)d_in[9];
    const float* bgx   = (const float*)d_in[10];
    const float* bbx   = (const float*)d_in[11];
    const float* bgh   = (const float*)d_in[12];
    const float* bbh   = (const float*)d_in[13];
    float* out = (float*)d_out;

    const int rnn_smem = (512 * SLICE + 64 * 64) * (int)sizeof(float);   // 65536 B
    cudaFuncSetAttribute(rnn_kernel, cudaFuncAttributeMaxDynamicSharedMemorySize, rnn_smem);

    // 1) px = xs @ Wx (both directions; dir=1 uses time-reversed xs)
    dim3 ggrid(G_ / 64, M_ / 128, 2);
    gemm_px_kernel<<<ggrid, 256>>>(xs, fWx, bWx);

    // 2) in-place LN3 on px
    ln3_kernel<<<2 * M_ * 3, 128>>>(fgx, fbx, bgx, bbx);

    // 3) persistent bidirectional GRU recurrence
    rnn_kernel<<<NBLK, 256, rnn_smem>>>(fWh, bWh, fgh, fbh, bgh, bbh, xmask, out);
}

// round 7
// speedup vs baseline: 1.0018x; 1.0018x over previous
#include <cuda_runtime.h>
#include <cstdint>
#include <cstddef>

// Problem constants
constexpr int B_ = 64;
constexpr int L_ = 512;
constexpr int E_ = 512;
constexpr int H_ = 512;
constexpr int G_ = 1536;          // 3*H
constexpr int M_ = B_ * L_;       // 32768 rows per direction
constexpr float LN_EPS = 1e-5f;

// Scratch (device globals: allocation-free)
__device__ float g_px[2ull * 32768ull * 1536ull];   // LN3(x @ Wx) per dir, [dir][b*L+s][1536]
__device__ float g_ph[2 * 64 * 1536];               // per-step h @ Wh, [dir][b][1536]
__device__ float g_hT[2 * 512 * 64];                // hidden state transposed [dir][k][b]
__device__ unsigned g_cnt;                          // grid barrier (zero-init)
__device__ unsigned g_gen;

// ---------------------------------------------------------------------------
// Kernel 1: px[dir][m][n] = sum_e xs[b][torig][e] * Wx_dir[e][n]
// BM=128, BN=64, BK=16, 256 threads, 8x4 per-thread tile.
// ---------------------------------------------------------------------------
__global__ __launch_bounds__(256) void gemm_px_kernel(
    const float* __restrict__ xs,
    const float* __restrict__ Wxf,
    const float* __restrict__ Wxb)
{
    constexpr int BM = 128, BN = 64, BK = 16, LDA = BM + 4;
    __shared__ float As[BK * LDA];
    __shared__ float Bs[BK * BN];

    const int dir = blockIdx.z;
    const float* W = dir ? Wxb : Wxf;
    const int m0 = blockIdx.y * BM;
    const int n0 = blockIdx.x * BN;
    const int t  = threadIdx.x;
    const int tx = t & 15;     // 16 col groups (4 cols each)
    const int ty = t >> 4;     // 16 row groups (8 rows each)

    float acc[8][4];
#pragma unroll
    for (int r = 0; r < 8; r++)
#pragma unroll
        for (int c = 0; c < 4; c++) acc[r][c] = 0.f;

    for (int kt = 0; kt < E_; kt += BK) {
        // Load A tile (gathered rows, reversed in t for dir=1)
#pragma unroll
        for (int i = 0; i < 2; i++) {
            int idx = t + 256 * i;        // 0..511 -> 128 rows x 4 float4
            int row = idx >> 2;
            int c4  = idx & 3;
            int m   = m0 + row;
            int b   = m >> 9;
            int s   = m & 511;
            int torig = dir ? (511 - s) : s;
            const float4 va = *reinterpret_cast<const float4*>(
                xs + ((size_t)(b * 512 + torig)) * 512 + kt + c4 * 4);
            As[(c4 * 4 + 0) * LDA + row] = va.x;
            As[(c4 * 4 + 1) * LDA + row] = va.y;
            As[(c4 * 4 + 2) * LDA + row] = va.z;
            As[(c4 * 4 + 3) * LDA + row] = va.w;
        }
        // Load B tile
        {
            int row = t >> 4;   // 0..15 (k)
            int c4  = t & 15;   // 16 float4 per row
            const float4 vb = *reinterpret_cast<const float4*>(
                W + (size_t)(kt + row) * G_ + n0 + c4 * 4);
            *reinterpret_cast<float4*>(Bs + row * BN + c4 * 4) = vb;
        }
        __syncthreads();

#pragma unroll
        for (int k = 0; k < BK; k++) {
            float4 a0 = *reinterpret_cast<const float4*>(As + k * LDA + ty * 8);
            float4 a1 = *reinterpret_cast<const float4*>(As + k * LDA + ty * 8 + 4);
            float4 bv = *reinterpret_cast<const float4*>(Bs + k * BN + tx * 4);
            float a[8] = {a0.x, a0.y, a0.z, a0.w, a1.x, a1.y, a1.z, a1.w};
            float bq[4] = {bv.x, bv.y, bv.z, bv.w};
#pragma unroll
            for (int r = 0; r < 8; r++)
#pragma unroll
                for (int c = 0; c < 4; c++) acc[r][c] += a[r] * bq[c];
        }
        __syncthreads();
    }

    float* C = g_px + (size_t)dir * M_ * G_;
#pragma unroll
    for (int r = 0; r < 8; r++) {
        float4 o;
        o.x = acc[r][0]; o.y = acc[r][1]; o.z = acc[r][2]; o.w = acc[r][3];
        *reinterpret_cast<float4*>(C + (size_t)(m0 + ty * 8 + r) * G_ + n0 + tx * 4) = o;
    }
}

// ---------------------------------------------------------------------------
// Kernel 2: in-place LN3 over g_px. One block per (row, chunk). 128 threads.
// ---------------------------------------------------------------------------
__global__ __launch_bounds__(128) void ln3_kernel(
    const float* __restrict__ gf, const float* __restrict__ bf,
    const float* __restrict__ gb, const float* __restrict__ bb)
{
    const int blk   = blockIdx.x;
    const int chunk = blk % 3;
    const int row   = blk / 3;          // 0..65535 (dir*32768 + m)
    const int dir   = row >> 15;
    const float* g  = (dir ? gb : gf) + chunk * 512;
    const float* be = (dir ? bb : bf) + chunk * 512;
    float* p = g_px + (size_t)row * G_ + chunk * 512;

    const int t = threadIdx.x;
    float4 v = reinterpret_cast<float4*>(p)[t];
    float s = v.x + v.y + v.z + v.w;
    float q = v.x * v.x + v.y * v.y + v.z * v.z + v.w * v.w;
#pragma unroll
    for (int o = 16; o > 0; o >>= 1) {
        s += __shfl_down_sync(0xffffffffu, s, o);
        q += __shfl_down_sync(0xffffffffu, q, o);
    }
    __shared__ float ss[4], sq[4];
    __shared__ float st[2];
    const int w = t >> 5, lane = t & 31;
    if (lane == 0) { ss[w] = s; sq[w] = q; }
    __syncthreads();
    if (t == 0) {
        float S = ss[0] + ss[1] + ss[2] + ss[3];
        float Q = sq[0] + sq[1] + sq[2] + sq[3];
        float mu = S * (1.f / 512.f);
        float var = Q * (1.f / 512.f) - mu * mu;
        st[0] = mu;
        st[1] = rsqrtf(var + LN_EPS);
    }
    __syncthreads();
    const float mu = st[0], rs = st[1];
    float4 gv = reinterpret_cast<const float4*>(g)[t];
    float4 bv = reinterpret_cast<const float4*>(be)[t];
    v.x = (v.x - mu) * rs * gv.x + bv.x;
    v.y = (v.y - mu) * rs * gv.y + bv.y;
    v.z = (v.z - mu) * rs * gv.z + bv.z;
    v.w = (v.w - mu) * rs * gv.w + bv.w;
    reinterpret_cast<float4*>(p)[t] = v;
}

// ---------------------------------------------------------------------------
// Kernel 3: persistent recurrence. Grid = 128 blocks (<= SM count -> all
// co-resident), 256 threads. Software grid barrier via global atomics.
//
// Per step:
//   Phase G: block (dir, slice) computes ph[dir][b][j0..j0+23] for all b,
//            with its Wh slice permanently in SMEM and hT staged via SMEM.
//   barrier
//   Phase U: block (dir, b) reads ph row, does LN3 stats + GRU gates,
//            keeps h in registers, writes hT (transposed) + output.
//   barrier
// ---------------------------------------------------------------------------
constexpr int NBLK  = 128;
constexpr int SLICE = 24;   // 64 slices * 24 = 1536

__device__ __forceinline__ void gridbar()
{
    __syncthreads();
    if (threadIdx.x == 0) {
        unsigned gen = *(volatile unsigned*)&g_gen;
        __threadfence();
        if (atomicAdd(&g_cnt, 1u) == NBLK - 1) {
            g_cnt = 0u;
            __threadfence();
            *(volatile unsigned*)&g_gen = gen + 1u;
        } else {
            while (*(volatile unsigned*)&g_gen == gen) { __nanosleep(64); }
            __threadfence();
        }
    }
    __syncthreads();
}

__global__ __launch_bounds__(256) void rnn_kernel(
    const float* __restrict__ Whf, const float* __restrict__ Whb,
    const float* __restrict__ ghf, const float* __restrict__ bhf,
    const float* __restrict__ ghb, const float* __restrict__ bhb,
    const float* __restrict__ mask, float* __restrict__ out)
{
    extern __shared__ float smem[];
    float* sWh = smem;                  // 512 * 24
    float* sh  = smem + 512 * SLICE;    // 64 * 64 staged hT chunk
    __shared__ float sred[48];
    __shared__ float sstat[6];

    const int t   = threadIdx.x;
    const int blk = blockIdx.x;
    const int dir = blk >> 6;
    const int sub = blk & 63;           // GEMM: slice id. Update: batch row.
    const float* Wh = dir ? Whb : Whf;
    const float* gh = dir ? ghb : ghf;
    const float* bh = dir ? bhb : bhf;
    const int j0 = sub * SLICE;

    // One-time: load persistent Wh slice into SMEM
    for (int i = t; i < 512 * SLICE; i += 256) {
        int k  = i / SLICE;
        int jj = i - k * SLICE;
        sWh[i] = Wh[(size_t)k * G_ + j0 + jj];
    }
    // One-time: zero hidden state (each block zeroes its 512-float slice)
    for (int i = t; i < 512; i += 256) g_hT[blk * 512 + i] = 0.f;

    // Update-phase constants (gains/biases for this thread's 6 columns)
    float gg6[6], bb6[6];
#pragma unroll
    for (int i = 0; i < 6; i++) {
        int j = (i >> 1) * 512 + (i & 1) * 256 + t;
        gg6[i] = gh[j];
        bb6[i] = bh[j];
    }
    const float* pxrow = g_px + ((size_t)(dir * 64 + sub)) * ((size_t)L_ * G_);
    const float* hTg = g_hT + dir * 512 * 64;
    float* phd = g_ph + dir * 64 * G_;
    const float* mrow = mask + sub * 512;

    float h0 = 0.f, h1 = 0.f;   // hidden state lives in registers (cols t, t+256)

    const int wj   = t >> 5;    // warp -> 3 consecutive j's
    const int lane = t & 31;    // lane -> 2 consecutive b's
    const float* wp = sWh + wj * 3;

    gridbar();   // hT zeros visible everywhere

    for (int s = 0; s < L_; s++) {
        // -------- Phase G: ph[b][j0+jloc] = sum_k hT[k][b] * Wh[k][j] --------
        float a00 = 0.f, a01 = 0.f, a10 = 0.f, a11 = 0.f, a20 = 0.f, a21 = 0.f;
        for (int k0 = 0; k0 < 512; k0 += 64) {
            const float4* src = reinterpret_cast<const float4*>(hTg + k0 * 64);
            float4* dst = reinterpret_cast<float4*>(sh);
#pragma unroll
            for (int i = 0; i < 4; i++) dst[t + 256 * i] = __ldcg(src + t + 256 * i);
            __syncthreads();
#pragma unroll 8
            for (int kk = 0; kk < 64; kk++) {
                const float* wr = wp + (k0 + kk) * SLICE;
                float w0 = wr[0], w1 = wr[1], w2 = wr[2];
                float2 hv = *reinterpret_cast<const float2*>(sh + kk * 64 + (lane << 1));
                a00 += w0 * hv.x; a01 += w0 * hv.y;
                a10 += w1 * hv.x; a11 += w1 * hv.y;
                a20 += w2 * hv.x; a21 += w2 * hv.y;
            }
            __syncthreads();
        }
        {
            int b0 = lane * 2;
            int jbase = j0 + wj * 3;
            float* pr0 = phd + (size_t)b0 * G_ + jbase;
            float* pr1 = pr0 + G_;
            pr0[0] = a00; pr0[1] = a10; pr0[2] = a20;
            pr1[0] = a01; pr1[1] = a11; pr1[2] = a21;
        }
        gridbar();

        // -------- Phase U: LN3(ph) + GRU gates for batch row `sub` --------
        const float* phr = phd + (size_t)sub * G_;
        float v0 = __ldcg(phr + t);
        float v1 = __ldcg(phr + 256 + t);
        float v2 = __ldcg(phr + 512 + t);
        float v3 = __ldcg(phr + 768 + t);
        float v4 = __ldcg(phr + 1024 + t);
        float v5 = __ldcg(phr + 1280 + t);

        float p0 = v0 + v1, p1 = v2 + v3, p2 = v4 + v5;
        float q0 = v0 * v0 + v1 * v1;
        float q1 = v2 * v2 + v3 * v3;
        float q2 = v4 * v4 + v5 * v5;
#pragma unroll
        for (int o = 16; o > 0; o >>= 1) {
            p0 += __shfl_down_sync(0xffffffffu, p0, o);
            p1 += __shfl_down_sync(0xffffffffu, p1, o);
            p2 += __shfl_down_sync(0xffffffffu, p2, o);
            q0 += __shfl_down_sync(0xffffffffu, q0, o);
            q1 += __shfl_down_sync(0xffffffffu, q1, o);
            q2 += __shfl_down_sync(0xffffffffu, q2, o);
        }
        if (lane == 0) {
            sred[wj * 6 + 0] = p0; sred[wj * 6 + 1] = p1; sred[wj * 6 + 2] = p2;
            sred[wj * 6 + 3] = q0; sred[wj * 6 + 4] = q1; sred[wj * 6 + 5] = q2;
        }
        __syncthreads();
        if (t < 6) {
            float tot = 0.f;
#pragma unroll
            for (int w = 0; w < 8; w++) tot += sred[w * 6 + t];
            sstat[t] = tot;
        }
        __syncthreads();
        const float mu0 = sstat[0] * (1.f / 512.f);
        const float mu1 = sstat[1] * (1.f / 512.f);
        const float mu2 = sstat[2] * (1.f / 512.f);
        const float rs0 = rsqrtf(sstat[3] * (1.f / 512.f) - mu0 * mu0 + LN_EPS);
        const float rs1 = rsqrtf(sstat[4] * (1.f / 512.f) - mu1 * mu1 + LN_EPS);
        const float rs2 = rsqrtf(sstat[5] * (1.f / 512.f) - mu2 * mu2 + LN_EPS);

        const int torig = dir ? (511 - s) : s;
        const float m = mrow[torig];
        const float* pxt = pxrow + (size_t)s * G_;
        float* outt = out + ((size_t)sub * 512 + torig) * 1024 + dir * 512;
        float* hwr = g_hT + dir * 512 * 64;

        // half 0: column c = t
        {
            float phz = (v0 - mu0) * rs0 * gg6[0] + bb6[0];
            float phrv = (v2 - mu1) * rs1 * gg6[2] + bb6[2];
            float phgv = (v4 - mu2) * rs2 * gg6[4] + bb6[4];
            float xz = pxt[t], xr = pxt[512 + t], xg = pxt[1024 + t];
            float z = 1.f / (1.f + __expf(-(xz + phz)));
            float r = 1.f / (1.f + __expf(-(xr + phrv)));
            float gv = tanhf(xg + r * phgv);
            h0 = h0 + m * z * (gv - h0);
            hwr[t * 64 + sub] = h0;
            outt[t] = h0 * m;
        }
        // half 1: column c = t + 256
        {
            int c = t + 256;
            float phz = (v1 - mu0) * rs0 * gg6[1] + bb6[1];
            float phrv = (v3 - mu1) * rs1 * gg6[3] + bb6[3];
            float phgv = (v5 - mu2) * rs2 * gg6[5] + bb6[5];
            float xz = pxt[c], xr = pxt[512 + c], xg = pxt[1024 + c];
            float z = 1.f / (1.f + __expf(-(xz + phz)));
            float r = 1.f / (1.f + __expf(-(xr + phrv)));
            float gv = tanhf(xg + r * phgv);
            h1 = h1 + m * z * (gv - h1);
            hwr[c * 64 + sub] = h1;
            outt[c] = h1 * m;
        }
        gridbar();
    }
}

// ---------------------------------------------------------------------------
extern "C" void kernel_launch(void* const* d_in, const int* in_sizes, int n_in,
                              void* d_out, int out_size)
{
    const float* xs    = (const float*)d_in[0];
    const float* xmask = (const float*)d_in[1];
    const float* fWx   = (const float*)d_in[2];
    const float* fWh   = (const float*)d_in[3];
    const float* fgx   = (const float*)d_in[4];
    const float* fbx   = (const float*)d_in[5];
    const float* fgh   = (const float*)d_in[6];
    const float* fbh   = (const float*)d_in[7];
    const float* bWx   = (const float*)d_in[8];
    const float* bWh   = (const float*)d_in[9];
    const float* bgx   = (const float*)d_in[10];
    const float* bbx   = (const float*)d_in[11];
    const float* bgh   = (const float*)d_in[12];
    const float* bbh   = (const float*)d_in[13];
    float* out = (float*)d_out;

    const int rnn_smem = (512 * SLICE + 64 * 64) * (int)sizeof(float);   // 65536 B
    cudaFuncSetAttribute(rnn_kernel, cudaFuncAttributeMaxDynamicSharedMemorySize, rnn_smem);

    // 1) px = xs @ Wx (both directions; dir=1 uses time-reversed xs)
    dim3 ggrid(G_ / 64, M_ / 128, 2);
    gemm_px_kernel<<<ggrid, 256>>>(xs, fWx, bWx);

    // 2) in-place LN3 on px
    ln3_kernel<<<2 * M_ * 3, 128>>>(fgx, fbx, bgx, bbx);

    // 3) persistent bidirectional GRU recurrence
    rnn_kernel<<<NBLK, 256, rnn_smem>>>(fWh, bWh, fgh, fbh, bgh, bbh, xmask, out);
}

// round 8
// speedup vs baseline: 1.5590x; 1.5563x over previous
#include <cuda_runtime.h>
#include <cstdint>
#include <cstddef>

using u64 = unsigned long long;

// Problem constants
constexpr int B_ = 64;
constexpr int L_ = 512;
constexpr int E_ = 512;
constexpr int G_ = 1536;          // 3*H
constexpr int M_ = B_ * L_;       // 32768 rows per direction
constexpr float LN_EPS = 1e-5f;

// Scratch (device globals: allocation-free)
__device__ float g_px[2ull * 32768ull * 1536ull];   // LN3(x @ Wx) per dir
__device__ float g_ph[2 * 64 * 1536];               // per-step h @ Wh
__device__ float g_hT[2 * 512 * 64];                // hidden transposed [dir][k][b]
__device__ unsigned g_cnt2[2];                      // per-dir grid barrier
__device__ unsigned g_gen2[2];

// ---------------- packed f32x2 helpers ----------------
__device__ __forceinline__ u64 pack2(float x, float y) {
    u64 r; asm("mov.b64 %0,{%1,%2};" : "=l"(r) : "f"(x), "f"(y)); return r;
}
__device__ __forceinline__ void unpack2(float& x, float& y, u64 v) {
    asm("mov.b64 {%0,%1},%2;" : "=f"(x), "=f"(y) : "l"(v));
}
__device__ __forceinline__ void fma2(u64& d, u64 a, u64 b) {
    asm("fma.rn.f32x2 %0,%1,%2,%0;" : "+l"(d) : "l"(a), "l"(b));
}
__device__ __forceinline__ u64 add2(u64 a, u64 b) {
    u64 d; asm("add.rn.f32x2 %0,%1,%2;" : "=l"(d) : "l"(a), "l"(b)); return d;
}

// ---------------------------------------------------------------------------
// Kernel 1: px = xs @ Wx.  BM=128, BN=128, BK=16, 256 threads.
// 8m x 8n thread tile; n organized as f32x2 pairs (natural u64 view of Bs),
// A broadcast + duplicated via mov.b64.
// ---------------------------------------------------------------------------
__global__ __launch_bounds__(256) void gemm_px_kernel(
    const float* __restrict__ xs,
    const float* __restrict__ Wxf,
    const float* __restrict__ Wxb)
{
    constexpr int BK = 16, LDA = 132;
    __shared__ float As[BK * LDA];     // A transposed [k][m]
    __shared__ float Bs[BK * 128];     // B [k][n]

    const int dir = blockIdx.z;
    const float* W = dir ? Wxb : Wxf;
    const int m0 = blockIdx.y * 128;
    const int n0 = blockIdx.x * 128;
    const int t  = threadIdx.x;
    const int tx = t & 15;     // 16 n-groups (4+4 cols)
    const int ty = t >> 4;     // 16 m-groups (8 rows)

    u64 acc[8][4];             // [m][n-pair]
#pragma unroll
    for (int m = 0; m < 8; m++)
#pragma unroll
        for (int np = 0; np < 4; np++) acc[m][np] = 0ull;

    for (int kt = 0; kt < E_; kt += BK) {
        // Load A tile (gathered rows, reversed in time for dir=1), transposed
#pragma unroll
        for (int i = 0; i < 2; i++) {
            int idx = t + 256 * i;        // 512 -> 128 rows x 4 float4
            int row = idx >> 2;
            int c4  = idx & 3;
            int m   = m0 + row;
            int b   = m >> 9;
            int s   = m & 511;
            int torig = dir ? (511 - s) : s;
            const float4 va = *reinterpret_cast<const float4*>(
                xs + ((size_t)(b * 512 + torig)) * 512 + kt + c4 * 4);
            As[(c4 * 4 + 0) * LDA + row] = va.x;
            As[(c4 * 4 + 1) * LDA + row] = va.y;
            As[(c4 * 4 + 2) * LDA + row] = va.z;
            As[(c4 * 4 + 3) * LDA + row] = va.w;
        }
        // Load B tile
#pragma unroll
        for (int i = 0; i < 2; i++) {
            int idx = t + 256 * i;
            int row = idx >> 5;   // 0..15
            int c4  = idx & 31;   // 32 float4 per 128-col row
            const float4 vb = *reinterpret_cast<const float4*>(
                W + (size_t)(kt + row) * G_ + n0 + c4 * 4);
            *reinterpret_cast<float4*>(Bs + row * 128 + c4 * 4) = vb;
        }
        __syncthreads();

#pragma unroll
        for (int k = 0; k < BK; k++) {
            float4 a0 = *reinterpret_cast<const float4*>(As + k * LDA + ty * 8);
            float4 a1 = *reinterpret_cast<const float4*>(As + k * LDA + ty * 8 + 4);
            u64 ad[8];
            ad[0] = pack2(a0.x, a0.x); ad[1] = pack2(a0.y, a0.y);
            ad[2] = pack2(a0.z, a0.z); ad[3] = pack2(a0.w, a0.w);
            ad[4] = pack2(a1.x, a1.x); ad[5] = pack2(a1.y, a1.y);
            ad[6] = pack2(a1.z, a1.z); ad[7] = pack2(a1.w, a1.w);
            const ulonglong2 q0 = *reinterpret_cast<const ulonglong2*>(Bs + k * 128 + tx * 4);
            const ulonglong2 q1 = *reinterpret_cast<const ulonglong2*>(Bs + k * 128 + 64 + tx * 4);
            u64 bp[4] = {q0.x, q0.y, q1.x, q1.y};
#pragma unroll
            for (int m = 0; m < 8; m++) {
                fma2(acc[m][0], ad[m], bp[0]);
                fma2(acc[m][1], ad[m], bp[1]);
                fma2(acc[m][2], ad[m], bp[2]);
                fma2(acc[m][3], ad[m], bp[3]);
            }
        }
        __syncthreads();
    }

    float* C = g_px + (size_t)dir * M_ * G_;
#pragma unroll
    for (int m = 0; m < 8; m++) {
        float* r = C + (size_t)(m0 + ty * 8 + m) * G_ + n0;
        ulonglong2 s0; s0.x = acc[m][0]; s0.y = acc[m][1];
        ulonglong2 s1; s1.x = acc[m][2]; s1.y = acc[m][3];
        *reinterpret_cast<ulonglong2*>(r + tx * 4)      = s0;
        *reinterpret_cast<ulonglong2*>(r + 64 + tx * 4) = s1;
    }
}

// ---------------------------------------------------------------------------
// Kernel 2: in-place LN3 over g_px. One block per (row, chunk). 128 threads.
// ---------------------------------------------------------------------------
__global__ __launch_bounds__(128) void ln3_kernel(
    const float* __restrict__ gf, const float* __restrict__ bf,
    const float* __restrict__ gb, const float* __restrict__ bb)
{
    const int blk   = blockIdx.x;
    const int chunk = blk % 3;
    const int row   = blk / 3;
    const int dir   = row >> 15;
    const float* g  = (dir ? gb : gf) + chunk * 512;
    const float* be = (dir ? bb : bf) + chunk * 512;
    float* p = g_px + (size_t)row * G_ + chunk * 512;

    const int t = threadIdx.x;
    float4 v = reinterpret_cast<float4*>(p)[t];
    float s = v.x + v.y + v.z + v.w;
    float q = v.x * v.x + v.y * v.y + v.z * v.z + v.w * v.w;
#pragma unroll
    for (int o = 16; o > 0; o >>= 1) {
        s += __shfl_down_sync(0xffffffffu, s, o);
        q += __shfl_down_sync(0xffffffffu, q, o);
    }
    __shared__ float ss[4], sq[4];
    __shared__ float st[2];
    const int w = t >> 5, lane = t & 31;
    if (lane == 0) { ss[w] = s; sq[w] = q; }
    __syncthreads();
    if (t == 0) {
        float S = ss[0] + ss[1] + ss[2] + ss[3];
        float Q = sq[0] + sq[1] + sq[2] + sq[3];
        float mu = S * (1.f / 512.f);
        float var = Q * (1.f / 512.f) - mu * mu;
        st[0] = mu;
        st[1] = rsqrtf(var + LN_EPS);
    }
    __syncthreads();
    const float mu = st[0], rs = st[1];
    float4 gv = reinterpret_cast<const float4*>(g)[t];
    float4 bv = reinterpret_cast<const float4*>(be)[t];
    v.x = (v.x - mu) * rs * gv.x + bv.x;
    v.y = (v.y - mu) * rs * gv.y + bv.y;
    v.z = (v.z - mu) * rs * gv.z + bv.z;
    v.w = (v.w - mu) * rs * gv.w + bv.w;
    reinterpret_cast<float4*>(p)[t] = v;
}

// ---------------------------------------------------------------------------
// Kernel 3: persistent recurrence, 128 blocks (1/SM), 256 threads.
// Per-direction software grid barrier (64 blocks each).
// ---------------------------------------------------------------------------
constexpr int SLICE = 24;

__device__ __forceinline__ void gridbar(int dir)
{
    __syncthreads();
    if (threadIdx.x == 0) {
        unsigned gen = *(volatile unsigned*)&g_gen2[dir];
        __threadfence();
        if (atomicAdd(&g_cnt2[dir], 1u) == 63u) {
            g_cnt2[dir] = 0u;
            __threadfence();
            *(volatile unsigned*)&g_gen2[dir] = gen + 1u;
        } else {
            while (*(volatile unsigned*)&g_gen2[dir] == gen) { __nanosleep(32); }
            __threadfence();
        }
    }
    __syncthreads();
}

__device__ __forceinline__ void stage_chunk(const float* gsrc, const float* dst, int t)
{
    unsigned saddr = (unsigned)__cvta_generic_to_shared(dst);
#pragma unroll
    for (int i = 0; i < 8; i++) {
        int off = (t + 256 * i) * 16;
        asm volatile("cp.async.cg.shared.global [%0], [%1], 16;"
                     :: "r"(saddr + off), "l"((const char*)gsrc + off) : "memory");
    }
    asm volatile("cp.async.commit_group;" ::: "memory");
}

__global__ __launch_bounds__(256) void rnn_kernel(
    const float* __restrict__ Whf, const float* __restrict__ Whb,
    const float* __restrict__ ghf, const float* __restrict__ bhf,
    const float* __restrict__ ghb, const float* __restrict__ bhb,
    const float* __restrict__ mask, float* __restrict__ out)
{
    extern __shared__ float smem[];
    float* sWh = smem;                    // [512][32] padded (j-groups of 8: 6 used)
    float* sh  = smem + 512 * 32;         // 2 x (128 k x 64 b) staging buffers
    __shared__ float sred[48];
    __shared__ float sstat[6];

    const int t   = threadIdx.x;
    const int blk = blockIdx.x;
    const int dir = blk >> 6;
    const int sub = blk & 63;             // G: j-slice id. U: batch row.
    const float* Wh = dir ? Whb : Whf;
    const float* gh = dir ? ghb : ghf;
    const float* bh = dir ? bhb : bhf;
    const int j0 = sub * SLICE;

    // G-phase thread decode: q = k-split (within chunk), jg = j-group, bg = b-group
    const int q  = t >> 6;
    const int jg = (t >> 4) & 3;
    const int bg = t & 15;
    const int pos = t & 63;

    // One-time: persistent Wh slice -> SMEM, padded [k][4][8]
    for (int i = t; i < 512 * SLICE; i += 256) {
        int k  = i / SLICE;
        int jj = i - k * SLICE;
        sWh[k * 32 + jj + (jj / 6) * 2] = Wh[(size_t)k * G_ + j0 + jj];
    }
    // One-time: zero this block's hT column range
    for (int i = t; i < 512; i += 256)
        g_hT[dir * 32768 + sub * 512 + i] = 0.f;

    // U-phase constants
    float gg6[6], bb6[6];
#pragma unroll
    for (int i = 0; i < 6; i++) {
        int j = (i >> 1) * 512 + (i & 1) * 256 + t;
        gg6[i] = gh[j];
        bb6[i] = bh[j];
    }
    const float* pxrow = g_px + ((size_t)(dir * 64 + sub)) * ((size_t)L_ * G_);
    const float* hTg = g_hT + dir * 32768;
    float* phd = g_ph + dir * 64 * G_;
    const float* mrow = mask + sub * 512;
    const int wj = t >> 5, lane = t & 31;

    float h0 = 0.f, h1 = 0.f;             // hidden state in registers (cols t, t+256)

    gridbar(dir);                          // hT zeros visible

    for (int s = 0; s < L_; s++) {
        // ---- prefetch U-phase inputs (used ~5us later) ----
        const int torig = dir ? (511 - s) : s;
        const float* pxt = pxrow + (size_t)s * G_;
        const float m   = __ldg(mrow + torig);
        const float xz0 = __ldg(pxt + t);
        const float xr0 = __ldg(pxt + 512 + t);
        const float xg0 = __ldg(pxt + 1024 + t);
        const float xz1 = __ldg(pxt + 256 + t);
        const float xr1 = __ldg(pxt + 768 + t);
        const float xg1 = __ldg(pxt + 1280 + t);

        // ---- Phase G: ph[b][j0..j0+23] = sum_k hT[k][b] * Wh[k][j] ----
        u64 a[12];                         // [jp*4 + b] packed (j-even, j-odd)
#pragma unroll
        for (int i = 0; i < 12; i++) a[i] = 0ull;

        stage_chunk(hTg,            sh,        t);   // chunk 0 -> buf0
        stage_chunk(hTg + 128 * 64, sh + 8192, t);   // chunk 1 -> buf1

        for (int c = 0; c < 4; c++) {
            if (c == 3) asm volatile("cp.async.wait_group 0;" ::: "memory");
            else        asm volatile("cp.async.wait_group 1;" ::: "memory");
            __syncthreads();

            const float* shc   = sh + (c & 1) * 8192;
            const float* wbase = sWh + (c * 128 + q * 32) * 32 + jg * 8;
            const float* hbase = shc + (q * 32) * 64 + bg * 4;
#pragma unroll 8
            for (int kk = 0; kk < 32; kk++) {
                const ulonglong2 wp01 = *reinterpret_cast<const ulonglong2*>(wbase + kk * 32);
                const u64 wp2 = *reinterpret_cast<const u64*>(wbase + kk * 32 + 4);
                const float4 hv = *reinterpret_cast<const float4*>(hbase + kk * 64);
                u64 hd0 = pack2(hv.x, hv.x);
                u64 hd1 = pack2(hv.y, hv.y);
                u64 hd2 = pack2(hv.z, hv.z);
                u64 hd3 = pack2(hv.w, hv.w);
                fma2(a[0], wp01.x, hd0); fma2(a[1], wp01.x, hd1);
                fma2(a[2], wp01.x, hd2); fma2(a[3], wp01.x, hd3);
                fma2(a[4], wp01.y, hd0); fma2(a[5], wp01.y, hd1);
                fma2(a[6], wp01.y, hd2); fma2(a[7], wp01.y, hd3);
                fma2(a[8], wp2,    hd0); fma2(a[9], wp2,    hd1);
                fma2(a[10], wp2,   hd2); fma2(a[11], wp2,   hd3);
            }
            __syncthreads();
            if (c < 2)
                stage_chunk(hTg + (c + 2) * 128 * 64, sh + (c & 1) * 8192, t);
        }

        // k-split reduction through buf0 (free now), then write ph
        {
            u64* red = reinterpret_cast<u64*>(sh);
            if (q) {
                u64* r = red + ((q - 1) * 64 + pos) * 12;
#pragma unroll
                for (int i = 0; i < 12; i++) r[i] = a[i];
            }
            __syncthreads();
            if (q == 0) {
#pragma unroll
                for (int w = 0; w < 3; w++) {
                    const u64* r = red + (w * 64 + pos) * 12;
#pragma unroll
                    for (int i = 0; i < 12; i++) a[i] = add2(a[i], r[i]);
                }
                const int jbase = j0 + jg * 6;
#pragma unroll
                for (int b = 0; b < 4; b++) {
                    u64* pr = reinterpret_cast<u64*>(phd + (size_t)(bg * 4 + b) * G_ + jbase);
                    pr[0] = a[b];
                    pr[1] = a[4 + b];
                    pr[2] = a[8 + b];
                }
            }
        }
        gridbar(dir);

        // ---- Phase U: LN3(ph) + GRU gates for batch row `sub` ----
        const float* phr = phd + (size_t)sub * G_;
        float v0 = __ldcg(phr + t);
        float v1 = __ldcg(phr + 256 + t);
        float v2 = __ldcg(phr + 512 + t);
        float v3 = __ldcg(phr + 768 + t);
        float v4 = __ldcg(phr + 1024 + t);
        float v5 = __ldcg(phr + 1280 + t);

        float p0 = v0 + v1, p1 = v2 + v3, p2 = v4 + v5;
        float q0 = v0 * v0 + v1 * v1;
        float q1 = v2 * v2 + v3 * v3;
        float q2 = v4 * v4 + v5 * v5;
#pragma unroll
        for (int o = 16; o > 0; o >>= 1) {
            p0 += __shfl_down_sync(0xffffffffu, p0, o);
            p1 += __shfl_down_sync(0xffffffffu, p1, o);
            p2 += __shfl_down_sync(0xffffffffu, p2, o);
            q0 += __shfl_down_sync(0xffffffffu, q0, o);
            q1 += __shfl_down_sync(0xffffffffu, q1, o);
            q2 += __shfl_down_sync(0xffffffffu, q2, o);
        }
        if (lane == 0) {
            sred[wj * 6 + 0] = p0; sred[wj * 6 + 1] = p1; sred[wj * 6 + 2] = p2;
            sred[wj * 6 + 3] = q0; sred[wj * 6 + 4] = q1; sred[wj * 6 + 5] = q2;
        }
        __syncthreads();
        if (t < 6) {
            float tot = 0.f;
#pragma unroll
            for (int w = 0; w < 8; w++) tot += sred[w * 6 + t];
            sstat[t] = tot;
        }
        __syncthreads();
        const float mu0 = sstat[0] * (1.f / 512.f);
        const float mu1 = sstat[1] * (1.f / 512.f);
        const float mu2 = sstat[2] * (1.f / 512.f);
        const float rs0 = rsqrtf(sstat[3] * (1.f / 512.f) - mu0 * mu0 + LN_EPS);
        const float rs1 = rsqrtf(sstat[4] * (1.f / 512.f) - mu1 * mu1 + LN_EPS);
        const float rs2 = rsqrtf(sstat[5] * (1.f / 512.f) - mu2 * mu2 + LN_EPS);

        float* outt = out + ((size_t)sub * 512 + torig) * 1024 + dir * 512;
        float* hwr = g_hT + dir * 32768;

        // half 0: column t
        {
            float phz  = (v0 - mu0) * rs0 * gg6[0] + bb6[0];
            float phrv = (v2 - mu1) * rs1 * gg6[2] + bb6[2];
            float phgv = (v4 - mu2) * rs2 * gg6[4] + bb6[4];
            float z  = 1.f / (1.f + __expf(-(xz0 + phz)));
            float r  = 1.f / (1.f + __expf(-(xr0 + phrv)));
            float gv = tanhf(xg0 + r * phgv);
            h0 = h0 + m * z * (gv - h0);
            hwr[t * 64 + sub] = h0;
            outt[t] = h0 * m;
        }
        // half 1: column t+256
        {
            float phz  = (v1 - mu0) * rs0 * gg6[1] + bb6[1];
            float phrv = (v3 - mu1) * rs1 * gg6[3] + bb6[3];
            float phgv = (v5 - mu2) * rs2 * gg6[5] + bb6[5];
            float z  = 1.f / (1.f + __expf(-(xz1 + phz)));
            float r  = 1.f / (1.f + __expf(-(xr1 + phrv)));
            float gv = tanhf(xg1 + r * phgv);
            h1 = h1 + m * z * (gv - h1);
            hwr[(t + 256) * 64 + sub] = h1;
            outt[t + 256] = h1 * m;
        }
        gridbar(dir);
    }
}

// ---------------------------------------------------------------------------
extern "C" void kernel_launch(void* const* d_in, const int* in_sizes, int n_in,
                              void* d_out, int out_size)
{
    const float* xs    = (const float*)d_in[0];
    const float* xmask = (const float*)d_in[1];
    const float* fWx   = (const float*)d_in[2];
    const float* fWh   = (const float*)d_in[3];
    const float* fgx   = (const float*)d_in[4];
    const float* fbx   = (const float*)d_in[5];
    const float* fgh   = (const float*)d_in[6];
    const float* fbh   = (const float*)d_in[7];
    const float* bWx   = (const float*)d_in[8];
    const float* bWh   = (const float*)d_in[9];
    const float* bgx   = (const float*)d_in[10];
    const float* bbx   = (const float*)d_in[11];
    const float* bgh   = (const float*)d_in[12];
    const float* bbh   = (const float*)d_in[13];
    float* out = (float*)d_out;

    // dynamic smem: Wh slice (512*32 floats) + 2 staging buffers (2*128*64)
    const int rnn_smem = (512 * 32 + 2 * 128 * 64) * (int)sizeof(float);  // 131072
    cudaFuncSetAttribute(rnn_kernel, cudaFuncAttributeMaxDynamicSharedMemorySize, rnn_smem);

    // 1) px = xs @ Wx (both directions; dir=1 uses time-reversed xs)
    dim3 ggrid(G_ / 128, M_ / 128, 2);
    gemm_px_kernel<<<ggrid, 256>>>(xs, fWx, bWx);

    // 2) in-place LN3 on px
    ln3_kernel<<<2 * M_ * 3, 128>>>(fgx, fbx, bgx, bbx);

    // 3) persistent bidirectional GRU recurrence
    rnn_kernel<<<128, 256, rnn_smem>>>(fWh, bWh, fgh, fbh, bgh, bbh, xmask, out);
}